// round 4
// baseline (speedup 1.0000x reference)
#include <cuda_runtime.h>

#define SSTEPS 8
#define NNODES 50000
#define D 128
#define NE 1600000

#define BM 128
#define PAD_AG 132   // sAgg row pitch (floats); 132*4B, 16B-aligned
#define PAD_X 20     // sX row pitch

// ---- device scratch (static; no runtime allocation) ----
__device__ __align__(16) int   g_deg[NNODES];
__device__ __align__(16) int   g_cursor[NNODES];
__device__ __align__(16) int   g_rowptr[NNODES + 1];
__device__ __align__(16) int   g_col[NE];
__device__ __align__(16) float g_invdeg[NNODES];
__device__ __align__(16) float g_WT[2 * D * D];   // [k][j]: k<128 -> W_l, else W_r

// ---------------- CSR build ----------------
__global__ void k_init() {
    int i = blockIdx.x * blockDim.x + threadIdx.x;
    if (i < NNODES) { g_deg[i] = 0; g_cursor[i] = 0; }
}

__global__ void k_count(const int* __restrict__ ei) {
    int e = blockIdx.x * blockDim.x + threadIdx.x;
    if (e < NE) atomicAdd(&g_deg[ei[NE + e]], 1);
}

__global__ void k_scan() {
    __shared__ int sbuf[256];
    __shared__ int s_carry;
    if (threadIdx.x == 0) s_carry = 0;
    __syncthreads();
    const int nchunk = (NNODES + 255) / 256;
    for (int c = 0; c < nchunk; c++) {
        int idx = c * 256 + threadIdx.x;
        int v = (idx < NNODES) ? g_deg[idx] : 0;
        sbuf[threadIdx.x] = v;
        __syncthreads();
        for (int off = 1; off < 256; off <<= 1) {
            int t = (threadIdx.x >= off) ? sbuf[threadIdx.x - off] : 0;
            __syncthreads();
            sbuf[threadIdx.x] += t;
            __syncthreads();
        }
        int carry = s_carry;
        if (idx < NNODES) {
            g_rowptr[idx] = carry + sbuf[threadIdx.x] - v;
            g_invdeg[idx] = 1.0f / (float)max(v, 1);
        }
        __syncthreads();
        if (threadIdx.x == 255) s_carry = carry + sbuf[255];
        __syncthreads();
    }
    if (threadIdx.x == 0) g_rowptr[NNODES] = s_carry;
}

__global__ void k_fill(const int* __restrict__ ei) {
    int e = blockIdx.x * blockDim.x + threadIdx.x;
    if (e < NE) {
        int src = ei[e];
        int dst = ei[NE + e];
        int pos = atomicAdd(&g_cursor[dst], 1);
        g_col[g_rowptr[dst] + pos] = src;
    }
}

__global__ void k_wt(const float* __restrict__ Wl, const float* __restrict__ Wr) {
    int i = blockIdx.x * blockDim.x + threadIdx.x;
    if (i < 2 * D * D) {
        int k = i / D, j = i % D;
        g_WT[i] = (k < D) ? Wl[j * D + k] : Wr[j * D + (k - D)];
    }
}

// ---------------- packed f32x2 helpers ----------------
#define FMA2(d, a, b) asm("fma.rn.f32x2 %0, %1, %2, %0;" : "+l"(d) : "l"(a), "l"(b))
#define PACK2(d, x, y) asm("mov.b64 %0, {%1, %2};" : "=l"(d) : "f"(x), "f"(y))
#define PACKBC(d, x)   asm("mov.b64 %0, {%1, %1};" : "=l"(d) : "f"(x))
#define UNPK2(x, y, d) asm("mov.b64 {%0, %1}, %2;" : "=f"(x), "=f"(y) : "l"(d))

// ---------------- fused gather + GEMM + head ----------------
// grid (ceil(N/128), S), 256 threads, dyn smem 86528 B, 2 blocks/SM
__global__ void __launch_bounds__(256, 2) k_fused(
    const float* __restrict__ input,
    const float* __restrict__ b_l,
    const float* __restrict__ W_fc,
    const float* __restrict__ b_fc,
    float* __restrict__ out)
{
    extern __shared__ float smem[];
    float* sAgg = smem;                       // 128*132
    float* sW   = sAgg + BM * PAD_AG;         // 16*128
    float* sX   = sW + 16 * 128;              // 128*20
    float* sYs  = sX + BM * PAD_X;            // 128

    const int s    = blockIdx.y;
    const int nb   = blockIdx.x * BM;
    const int tid  = threadIdx.x;
    const int lane = tid & 31;
    const int wrp  = tid >> 5;
    const float* xs_base = input + (size_t)s * NNODES * D;

    // ---- Phase A: gather mean aggregation into smem (one warp per node) ----
    for (int ni = wrp; ni < BM; ni += 8) {
        int n = nb + ni;
        float ax = 0.f, ay = 0.f, az = 0.f, aw = 0.f;
        if (n < NNODES) {
            int beg = g_rowptr[n];
            int end = g_rowptr[n + 1];
            const float* bp = xs_base + lane * 4;
            int j = beg;
            for (; j + 4 <= end; j += 4) {
                int c0 = g_col[j], c1 = g_col[j + 1], c2 = g_col[j + 2], c3 = g_col[j + 3];
                float4 v0 = *(const float4*)(bp + (size_t)c0 * D);
                float4 v1 = *(const float4*)(bp + (size_t)c1 * D);
                float4 v2 = *(const float4*)(bp + (size_t)c2 * D);
                float4 v3 = *(const float4*)(bp + (size_t)c3 * D);
                ax += v0.x + v1.x + v2.x + v3.x;
                ay += v0.y + v1.y + v2.y + v3.y;
                az += v0.z + v1.z + v2.z + v3.z;
                aw += v0.w + v1.w + v2.w + v3.w;
            }
            for (; j < end; j++) {
                float4 v = *(const float4*)(bp + (size_t)g_col[j] * D);
                ax += v.x; ay += v.y; az += v.z; aw += v.w;
            }
            float inv = g_invdeg[n];
            ax *= inv; ay *= inv; az *= inv; aw *= inv;
        }
        *(float4*)&sAgg[ni * PAD_AG + lane * 4] = make_float4(ax, ay, az, aw);
    }
    __syncthreads();

    // ---- Phase B: GEMM  xs[m][j] = sum_k cat(agg,x)[m][k] * WT[k][j] ----
    const int tx = tid & 15;   // j / 8
    const int ty = tid >> 4;   // m / 8
    unsigned long long acc2[8][4];
#pragma unroll
    for (int i = 0; i < 8; i++)
#pragma unroll
        for (int p = 0; p < 4; p++) acc2[i][p] = 0ull;

    const int lm  = tid >> 1;
    const int lks = (tid & 1) * 8;

#define GEMM_CHUNK(BUF, PITCH, KOFF)                                          \
    _Pragma("unroll")                                                         \
    for (int kl = 0; kl < 16; kl++) {                                         \
        float4 wv0 = *(const float4*)&sW[kl * 128 + tx * 8];                  \
        float4 wv1 = *(const float4*)&sW[kl * 128 + tx * 8 + 4];              \
        unsigned long long wp0, wp1, wp2, wp3;                                \
        PACK2(wp0, wv0.x, wv0.y); PACK2(wp1, wv0.z, wv0.w);                   \
        PACK2(wp2, wv1.x, wv1.y); PACK2(wp3, wv1.z, wv1.w);                   \
        _Pragma("unroll")                                                     \
        for (int i = 0; i < 8; i++) {                                         \
            float a = (BUF)[(ty * 8 + i) * (PITCH) + (KOFF) + kl];            \
            unsigned long long ap; PACKBC(ap, a);                             \
            FMA2(acc2[i][0], ap, wp0);                                        \
            FMA2(acc2[i][1], ap, wp1);                                        \
            FMA2(acc2[i][2], ap, wp2);                                        \
            FMA2(acc2[i][3], ap, wp3);                                        \
        }                                                                     \
    }

    for (int kc = 0; kc < 16; kc++) {
        // prefetch W chunk (and x chunk for kc >= 8)
        float4 w0 = *(const float4*)&g_WT[kc * 16 * 128 + tid * 8];
        float4 w1 = *(const float4*)&g_WT[kc * 16 * 128 + tid * 8 + 4];
        float4 x0 = make_float4(0, 0, 0, 0), x1 = make_float4(0, 0, 0, 0);
        if (kc >= 8) {
            int n = nb + lm;
            if (n < NNODES) {
                const float* p = xs_base + (size_t)n * D + (kc - 8) * 16 + lks;
                x0 = *(const float4*)p;
                x1 = *(const float4*)(p + 4);
            }
        }
        __syncthreads();   // previous sW/sX consumed
        *(float4*)&sW[tid * 8]     = w0;
        *(float4*)&sW[tid * 8 + 4] = w1;
        if (kc >= 8) {
            *(float4*)&sX[lm * PAD_X + lks]     = x0;
            *(float4*)&sX[lm * PAD_X + lks + 4] = x1;
        }
        __syncthreads();

        if (kc < 8) { GEMM_CHUNK(sAgg, PAD_AG, kc * 16) }
        else        { GEMM_CHUNK(sX, PAD_X, 0) }
    }

    // ---- epilogue: + b_l, write xs, compute ys ----
    float4 bl0 = *(const float4*)&b_l[tx * 8];
    float4 bl1 = *(const float4*)&b_l[tx * 8 + 4];
    float bl[8] = { bl0.x, bl0.y, bl0.z, bl0.w, bl1.x, bl1.y, bl1.z, bl1.w };
    float4 wf0 = *(const float4*)&W_fc[tx * 8];
    float4 wf1 = *(const float4*)&W_fc[tx * 8 + 4];
    float wf[8] = { wf0.x, wf0.y, wf0.z, wf0.w, wf1.x, wf1.y, wf1.z, wf1.w };

#pragma unroll
    for (int i = 0; i < 8; i++) {
        int m = ty * 8 + i;
        int n = nb + m;
        float xsv[8];
#pragma unroll
        for (int p = 0; p < 4; p++) UNPK2(xsv[2 * p], xsv[2 * p + 1], acc2[i][p]);
        float pacc = 0.f;
#pragma unroll
        for (int jj = 0; jj < 8; jj++) {
            xsv[jj] += bl[jj];
            pacc += xsv[jj] * wf[jj];
        }
        for (int off = 8; off > 0; off >>= 1)
            pacc += __shfl_down_sync(0xffffffffu, pacc, off, 16);
        if (tx == 0) sYs[m] = pacc;
        if (n < NNODES) {
            float* op = out + ((size_t)s * NNODES + n) * D + tx * 8;
            *(float4*)op       = make_float4(xsv[0], xsv[1], xsv[2], xsv[3]);
            *(float4*)(op + 4) = make_float4(xsv[4], xsv[5], xsv[6], xsv[7]);
        }
    }
    __syncthreads();
    if (tid < BM) {
        int n = nb + tid;
        if (n < NNODES)
            out[(size_t)SSTEPS * NNODES * D + (size_t)s * NNODES + n] = sYs[tid] + b_fc[0];
    }
}

// ---------------- launch ----------------
extern "C" void kernel_launch(void* const* d_in, const int* in_sizes, int n_in,
                              void* d_out, int out_size) {
    const float* input = (const float*)d_in[0];
    const int*   ei    = (const int*)d_in[1];      // int32 (JAX x64 disabled)
    const float* W_l   = (const float*)d_in[2];
    const float* b_l   = (const float*)d_in[3];
    const float* W_r   = (const float*)d_in[4];
    const float* W_fc  = (const float*)d_in[5];
    const float* b_fc  = (const float*)d_in[6];
    float* out = (float*)d_out;

    k_init <<<(NNODES + 255) / 256, 256>>>();
    k_count<<<(NE + 255) / 256, 256>>>(ei);
    k_scan <<<1, 256>>>();
    k_fill <<<(NE + 255) / 256, 256>>>(ei);
    k_wt   <<<(2 * D * D + 255) / 256, 256>>>(W_l, W_r);

    const int smem_bytes = (BM * PAD_AG + 16 * 128 + BM * PAD_X + BM) * sizeof(float);
    cudaFuncSetAttribute(k_fused, cudaFuncAttributeMaxDynamicSharedMemorySize, smem_bytes);
    dim3 grid((NNODES + BM - 1) / BM, SSTEPS);
    k_fused<<<grid, 256, smem_bytes>>>(input, b_l, W_fc, b_fc, out);
}

// round 5
// speedup vs baseline: 1.0442x; 1.0442x over previous
#include <cuda_runtime.h>
#include <cuda_fp16.h>

#define SSTEPS 8
#define NNODES 50000
#define D 128
#define NE 1600000

#define BM 128
#define PAD_A 20   // sA row pitch in floats (80 B)

// ---- device scratch (static; no runtime allocation) ----
__device__ __align__(16) int    g_deg[NNODES];
__device__ __align__(16) int    g_cursor[NNODES];
__device__ __align__(16) int    g_rowptr[NNODES + 1];
__device__ __align__(16) int    g_col[NE];
__device__ __align__(16) float  g_invdeg[NNODES];
__device__ __align__(16) float  g_WT[2 * D * D];                       // [k][j]
__device__ __align__(16) __half g_xh[(size_t)SSTEPS * NNODES * D];     // fp16 feature cache
__device__ __align__(16) float  g_agg[(size_t)SSTEPS * NNODES * D];    // mean agg (fp32)

// ---------------- CSR build ----------------
__global__ void k_init() {
    int i = blockIdx.x * blockDim.x + threadIdx.x;
    if (i < NNODES) { g_deg[i] = 0; g_cursor[i] = 0; }
}

__global__ void k_count(const int* __restrict__ ei) {
    int e = blockIdx.x * blockDim.x + threadIdx.x;
    if (e < NE) atomicAdd(&g_deg[ei[NE + e]], 1);
}

__global__ void k_scan() {
    __shared__ int sbuf[256];
    __shared__ int s_carry;
    if (threadIdx.x == 0) s_carry = 0;
    __syncthreads();
    const int nchunk = (NNODES + 255) / 256;
    for (int c = 0; c < nchunk; c++) {
        int idx = c * 256 + threadIdx.x;
        int v = (idx < NNODES) ? g_deg[idx] : 0;
        sbuf[threadIdx.x] = v;
        __syncthreads();
        for (int off = 1; off < 256; off <<= 1) {
            int t = (threadIdx.x >= off) ? sbuf[threadIdx.x - off] : 0;
            __syncthreads();
            sbuf[threadIdx.x] += t;
            __syncthreads();
        }
        int carry = s_carry;
        if (idx < NNODES) {
            g_rowptr[idx] = carry + sbuf[threadIdx.x] - v;
            g_invdeg[idx] = 1.0f / (float)max(v, 1);
        }
        __syncthreads();
        if (threadIdx.x == 255) s_carry = carry + sbuf[255];
        __syncthreads();
    }
    if (threadIdx.x == 0) g_rowptr[NNODES] = s_carry;
}

__global__ void k_fill(const int* __restrict__ ei) {
    int e = blockIdx.x * blockDim.x + threadIdx.x;
    if (e < NE) {
        int src = ei[e];
        int dst = ei[NE + e];
        int pos = atomicAdd(&g_cursor[dst], 1);
        g_col[g_rowptr[dst] + pos] = src;
    }
}

__global__ void k_wt(const float* __restrict__ Wl, const float* __restrict__ Wr) {
    int i = blockIdx.x * blockDim.x + threadIdx.x;
    if (i < 2 * D * D) {
        int k = i / D, j = i % D;
        g_WT[i] = (k < D) ? Wl[j * D + k] : Wr[j * D + (k - D)];
    }
}

// ---------------- fp32 -> fp16 feature cache ----------------
__global__ void __launch_bounds__(256) k_tohalf(const float* __restrict__ input) {
    size_t i = (size_t)(blockIdx.x * blockDim.x + threadIdx.x) * 4;
    const size_t total = (size_t)SSTEPS * NNODES * D;
    if (i < total) {
        float4 v = *(const float4*)(input + i);
        __half2 h0 = __floats2half2_rn(v.x, v.y);
        __half2 h1 = __floats2half2_rn(v.z, v.w);
        uint2 u;
        u.x = *reinterpret_cast<unsigned*>(&h0);
        u.y = *reinterpret_cast<unsigned*>(&h1);
        *(uint2*)(g_xh + i) = u;
    }
}

// ---------------- gather mean aggregation (fp16 reads, fp32 accum) ----------------
// one warp per node; lane covers 4 features (8 B); grid.y = step
__global__ void __launch_bounds__(256) k_agg() {
    int gw = (blockIdx.x * blockDim.x + threadIdx.x) >> 5;
    int lane = threadIdx.x & 31;
    if (gw >= NNODES) return;
    int n = gw;
    int s = blockIdx.y;
    const __half* bp = g_xh + (size_t)s * NNODES * D + lane * 4;

    int beg = g_rowptr[n];
    int end = g_rowptr[n + 1];
    float ax = 0.f, ay = 0.f, az = 0.f, aw = 0.f;

#define ACC_EDGE(c) {                                                   \
        uint2 u = *(const uint2*)(bp + (size_t)(c) * D);                \
        __half2 h0 = *reinterpret_cast<__half2*>(&u.x);                 \
        __half2 h1 = *reinterpret_cast<__half2*>(&u.y);                 \
        float2 f0 = __half22float2(h0);                                 \
        float2 f1 = __half22float2(h1);                                 \
        ax += f0.x; ay += f0.y; az += f1.x; aw += f1.y; }

    int j = beg;
    for (; j + 4 <= end; j += 4) {
        int c0 = g_col[j], c1 = g_col[j + 1], c2 = g_col[j + 2], c3 = g_col[j + 3];
        ACC_EDGE(c0) ACC_EDGE(c1) ACC_EDGE(c2) ACC_EDGE(c3)
    }
    for (; j < end; j++) { int c = g_col[j]; ACC_EDGE(c) }
#undef ACC_EDGE

    float inv = g_invdeg[n];
    float4 r = make_float4(ax * inv, ay * inv, az * inv, aw * inv);
    *(float4*)&g_agg[((size_t)s * NNODES + n) * D + lane * 4] = r;
}

// ---------------- packed f32x2 helpers ----------------
#define FMA2(d, a, b) asm("fma.rn.f32x2 %0, %1, %2, %0;" : "+l"(d) : "l"(a), "l"(b))
#define PACK2(d, x, y) asm("mov.b64 %0, {%1, %2};" : "=l"(d) : "f"(x), "f"(y))
#define PACKBC(d, x)   asm("mov.b64 %0, {%1, %1};" : "=l"(d) : "f"(x))
#define UNPK2(x, y, d) asm("mov.b64 {%0, %1}, %2;" : "=f"(x), "=f"(y) : "l"(d))

// ---------------- GEMM + head ----------------
// grid (ceil(N/128), S), 256 threads, static smem ~19 KB
__global__ void __launch_bounds__(256) k_gemm(
    const float* __restrict__ input,
    const float* __restrict__ b_l,
    const float* __restrict__ W_fc,
    const float* __restrict__ b_fc,
    float* __restrict__ out)
{
    __shared__ float sA[BM * PAD_A];
    __shared__ float sW[16 * 128];
    __shared__ float sYs[BM];

    const int s   = blockIdx.y;
    const int nb  = blockIdx.x * BM;
    const int tid = threadIdx.x;
    const int tx  = tid & 15;
    const int ty  = tid >> 4;
    const float* xs_base = input + (size_t)s * NNODES * D;
    const float* ag_base = g_agg + (size_t)s * NNODES * D;

    unsigned long long acc2[8][4];
#pragma unroll
    for (int i = 0; i < 8; i++)
#pragma unroll
        for (int p = 0; p < 4; p++) acc2[i][p] = 0ull;

    const int lm  = tid >> 1;
    const int lks = (tid & 1) * 8;

    for (int kc = 0; kc < 16; kc++) {
        float4 a0 = make_float4(0, 0, 0, 0), a1 = make_float4(0, 0, 0, 0);
        int n = nb + lm;
        if (n < NNODES) {
            const float* src = (kc < 8)
                ? ag_base + (size_t)n * D + kc * 16 + lks
                : xs_base + (size_t)n * D + (kc - 8) * 16 + lks;
            a0 = *(const float4*)src;
            a1 = *(const float4*)(src + 4);
        }
        float4 w0 = *(const float4*)&g_WT[kc * 16 * 128 + tid * 8];
        float4 w1 = *(const float4*)&g_WT[kc * 16 * 128 + tid * 8 + 4];

        __syncthreads();
        *(float4*)&sA[lm * PAD_A + lks]     = a0;
        *(float4*)&sA[lm * PAD_A + lks + 4] = a1;
        *(float4*)&sW[tid * 8]     = w0;
        *(float4*)&sW[tid * 8 + 4] = w1;
        __syncthreads();

#pragma unroll
        for (int kl = 0; kl < 16; kl++) {
            float4 wv0 = *(const float4*)&sW[kl * 128 + tx * 8];
            float4 wv1 = *(const float4*)&sW[kl * 128 + tx * 8 + 4];
            unsigned long long wp0, wp1, wp2, wp3;
            PACK2(wp0, wv0.x, wv0.y); PACK2(wp1, wv0.z, wv0.w);
            PACK2(wp2, wv1.x, wv1.y); PACK2(wp3, wv1.z, wv1.w);
#pragma unroll
            for (int i = 0; i < 8; i++) {
                float a = sA[(ty * 8 + i) * PAD_A + kl];
                unsigned long long ap; PACKBC(ap, a);
                FMA2(acc2[i][0], ap, wp0);
                FMA2(acc2[i][1], ap, wp1);
                FMA2(acc2[i][2], ap, wp2);
                FMA2(acc2[i][3], ap, wp3);
            }
        }
    }

    // epilogue
    float4 bl0 = *(const float4*)&b_l[tx * 8];
    float4 bl1 = *(const float4*)&b_l[tx * 8 + 4];
    float bl[8] = { bl0.x, bl0.y, bl0.z, bl0.w, bl1.x, bl1.y, bl1.z, bl1.w };
    float4 wf0 = *(const float4*)&W_fc[tx * 8];
    float4 wf1 = *(const float4*)&W_fc[tx * 8 + 4];
    float wf[8] = { wf0.x, wf0.y, wf0.z, wf0.w, wf1.x, wf1.y, wf1.z, wf1.w };

#pragma unroll
    for (int i = 0; i < 8; i++) {
        int m = ty * 8 + i;
        int n = nb + m;
        float xsv[8];
#pragma unroll
        for (int p = 0; p < 4; p++) UNPK2(xsv[2 * p], xsv[2 * p + 1], acc2[i][p]);
        float pacc = 0.f;
#pragma unroll
        for (int jj = 0; jj < 8; jj++) {
            xsv[jj] += bl[jj];
            pacc += xsv[jj] * wf[jj];
        }
        for (int off = 8; off > 0; off >>= 1)
            pacc += __shfl_down_sync(0xffffffffu, pacc, off, 16);
        if (tx == 0) sYs[m] = pacc;
        if (n < NNODES) {
            float* op = out + ((size_t)s * NNODES + n) * D + tx * 8;
            *(float4*)op       = make_float4(xsv[0], xsv[1], xsv[2], xsv[3]);
            *(float4*)(op + 4) = make_float4(xsv[4], xsv[5], xsv[6], xsv[7]);
        }
    }
    __syncthreads();
    if (tid < BM) {
        int n = nb + tid;
        if (n < NNODES)
            out[(size_t)SSTEPS * NNODES * D + (size_t)s * NNODES + n] = sYs[tid] + b_fc[0];
    }
}

// ---------------- launch ----------------
extern "C" void kernel_launch(void* const* d_in, const int* in_sizes, int n_in,
                              void* d_out, int out_size) {
    const float* input = (const float*)d_in[0];
    const int*   ei    = (const int*)d_in[1];      // int32 (JAX x64 disabled)
    const float* W_l   = (const float*)d_in[2];
    const float* b_l   = (const float*)d_in[3];
    const float* W_r   = (const float*)d_in[4];
    const float* W_fc  = (const float*)d_in[5];
    const float* b_fc  = (const float*)d_in[6];
    float* out = (float*)d_out;

    k_init <<<(NNODES + 255) / 256, 256>>>();
    k_count<<<(NE + 255) / 256, 256>>>(ei);
    k_scan <<<1, 256>>>();
    k_fill <<<(NE + 255) / 256, 256>>>(ei);
    k_wt   <<<(2 * D * D + 255) / 256, 256>>>(W_l, W_r);

    const size_t total = (size_t)SSTEPS * NNODES * D;
    k_tohalf<<<(unsigned)((total / 4 + 255) / 256), 256>>>(input);

    dim3 agrid((NNODES * 32 + 255) / 256, SSTEPS);
    k_agg<<<agrid, 256>>>();

    dim3 ggrid((NNODES + BM - 1) / BM, SSTEPS);
    k_gemm<<<ggrid, 256>>>(input, b_l, W_fc, b_fc, out);
}

// round 6
// speedup vs baseline: 1.1413x; 1.0930x over previous
#include <cuda_runtime.h>
#include <cuda_fp16.h>

#define SSTEPS 8
#define NNODES 50000
#define D 128
#define NE 1600000

#define BM 128
#define PAD_A 20   // sA row pitch in floats (80 B)

// ---- device scratch (static; no runtime allocation) ----
__device__ __align__(16) int    g_deg[NNODES];
__device__ __align__(16) int    g_cursor[NNODES];
__device__ __align__(16) int    g_rowptr[NNODES + 1];
__device__ __align__(16) int    g_col[NE];
__device__ __align__(16) float  g_invdeg[NNODES];
__device__ __align__(16) float  g_WT[2 * D * D];                       // [k][j]
__device__ __align__(16) __half g_xh[(size_t)SSTEPS * NNODES * D];     // fp16 feature cache
__device__ __align__(16) float  g_agg[(size_t)SSTEPS * NNODES * D];    // mean agg (fp32)

// ---------------- CSR build ----------------
__global__ void k_init() {
    int i = blockIdx.x * blockDim.x + threadIdx.x;
    if (i < NNODES) { g_deg[i] = 0; g_cursor[i] = 0; }
}

__global__ void k_count(const int* __restrict__ ei) {
    int e4 = (blockIdx.x * blockDim.x + threadIdx.x) * 4;
    if (e4 < NE) {
        int4 d = *(const int4*)(ei + NE + e4);
        atomicAdd(&g_deg[d.x], 1);
        atomicAdd(&g_deg[d.y], 1);
        atomicAdd(&g_deg[d.z], 1);
        atomicAdd(&g_deg[d.w], 1);
    }
}

__global__ void k_scan() {
    __shared__ int sbuf[256];
    __shared__ int s_carry;
    if (threadIdx.x == 0) s_carry = 0;
    __syncthreads();
    const int nchunk = (NNODES + 255) / 256;
    for (int c = 0; c < nchunk; c++) {
        int idx = c * 256 + threadIdx.x;
        int v = (idx < NNODES) ? g_deg[idx] : 0;
        sbuf[threadIdx.x] = v;
        __syncthreads();
        for (int off = 1; off < 256; off <<= 1) {
            int t = (threadIdx.x >= off) ? sbuf[threadIdx.x - off] : 0;
            __syncthreads();
            sbuf[threadIdx.x] += t;
            __syncthreads();
        }
        int carry = s_carry;
        if (idx < NNODES) {
            g_rowptr[idx] = carry + sbuf[threadIdx.x] - v;
            g_invdeg[idx] = 1.0f / (float)max(v, 1);
        }
        __syncthreads();
        if (threadIdx.x == 255) s_carry = carry + sbuf[255];
        __syncthreads();
    }
    if (threadIdx.x == 0) g_rowptr[NNODES] = s_carry;
}

__global__ void k_fill(const int* __restrict__ ei) {
    int e4 = (blockIdx.x * blockDim.x + threadIdx.x) * 4;
    if (e4 < NE) {
        int4 s = *(const int4*)(ei + e4);
        int4 d = *(const int4*)(ei + NE + e4);
        int p;
        p = atomicAdd(&g_cursor[d.x], 1); g_col[g_rowptr[d.x] + p] = s.x;
        p = atomicAdd(&g_cursor[d.y], 1); g_col[g_rowptr[d.y] + p] = s.y;
        p = atomicAdd(&g_cursor[d.z], 1); g_col[g_rowptr[d.z] + p] = s.z;
        p = atomicAdd(&g_cursor[d.w], 1); g_col[g_rowptr[d.w] + p] = s.w;
    }
}

__global__ void k_wt(const float* __restrict__ Wl, const float* __restrict__ Wr) {
    int i = blockIdx.x * blockDim.x + threadIdx.x;
    if (i < 2 * D * D) {
        int k = i / D, j = i % D;
        g_WT[i] = (k < D) ? Wl[j * D + k] : Wr[j * D + (k - D)];
    }
}

// ---------------- fp32 -> fp16 feature cache ----------------
__global__ void __launch_bounds__(256) k_tohalf(const float* __restrict__ input) {
    size_t i = (size_t)(blockIdx.x * blockDim.x + threadIdx.x) * 4;
    const size_t total = (size_t)SSTEPS * NNODES * D;
    if (i < total) {
        float4 v = *(const float4*)(input + i);
        __half2 h0 = __floats2half2_rn(v.x, v.y);
        __half2 h1 = __floats2half2_rn(v.z, v.w);
        uint2 u;
        u.x = *reinterpret_cast<unsigned*>(&h0);
        u.y = *reinterpret_cast<unsigned*>(&h1);
        *(uint2*)(g_xh + i) = u;
    }
}

// ---------------- gather mean aggregation ----------------
// one warp per node; half-warp per edge; each lane: 16B = 8 fp16 features.
__global__ void __launch_bounds__(256) k_agg() {
    int gw = (blockIdx.x * blockDim.x + threadIdx.x) >> 5;
    if (gw >= NNODES) return;
    const int lane = threadIdx.x & 31;
    const int h = lane >> 4;        // which edge of the pair
    const int q = lane & 15;        // feature group: halves 8q..8q+7
    const int n = gw;
    const int s = blockIdx.y;
    const __half* bp = g_xh + (size_t)s * NNODES * D + q * 8;

    float acc[8];
#pragma unroll
    for (int i = 0; i < 8; i++) acc[i] = 0.f;

#define ACC_U4(u) {                                                        \
        __half2 p0 = *reinterpret_cast<__half2*>(&u.x);                    \
        __half2 p1 = *reinterpret_cast<__half2*>(&u.y);                    \
        __half2 p2 = *reinterpret_cast<__half2*>(&u.z);                    \
        __half2 p3 = *reinterpret_cast<__half2*>(&u.w);                    \
        float2 f0 = __half22float2(p0); float2 f1 = __half22float2(p1);    \
        float2 f2 = __half22float2(p2); float2 f3 = __half22float2(p3);    \
        acc[0] += f0.x; acc[1] += f0.y; acc[2] += f1.x; acc[3] += f1.y;    \
        acc[4] += f2.x; acc[5] += f2.y; acc[6] += f3.x; acc[7] += f3.y; }

    const int beg = g_rowptr[n];
    const int end = g_rowptr[n + 1];
    int j = beg;
    // 4 pairs (8 edges) in flight
    for (; j + 8 <= end; j += 8) {
        int c0 = g_col[j + 0 + h];
        int c1 = g_col[j + 2 + h];
        int c2 = g_col[j + 4 + h];
        int c3 = g_col[j + 6 + h];
        uint4 u0 = *(const uint4*)(bp + (size_t)c0 * D);
        uint4 u1 = *(const uint4*)(bp + (size_t)c1 * D);
        uint4 u2 = *(const uint4*)(bp + (size_t)c2 * D);
        uint4 u3 = *(const uint4*)(bp + (size_t)c3 * D);
        ACC_U4(u0) ACC_U4(u1) ACC_U4(u2) ACC_U4(u3)
    }
    for (; j + 2 <= end; j += 2) {
        int c = g_col[j + h];
        uint4 u = *(const uint4*)(bp + (size_t)c * D);
        ACC_U4(u)
    }
    if (j < end && h == 0) {
        int c = g_col[j];
        uint4 u = *(const uint4*)(bp + (size_t)c * D);
        ACC_U4(u)
    }
#undef ACC_U4

    // combine the two half-warps (features identical, different edges)
#pragma unroll
    for (int i = 0; i < 8; i++)
        acc[i] += __shfl_down_sync(0xffffffffu, acc[i], 16);

    if (h == 0) {
        float inv = g_invdeg[n];
        float* op = g_agg + ((size_t)s * NNODES + n) * D + q * 8;
        *(float4*)op       = make_float4(acc[0] * inv, acc[1] * inv, acc[2] * inv, acc[3] * inv);
        *(float4*)(op + 4) = make_float4(acc[4] * inv, acc[5] * inv, acc[6] * inv, acc[7] * inv);
    }
}

// ---------------- GEMM + head (R3 scalar form) ----------------
__global__ void __launch_bounds__(256) k_gemm(
    const float* __restrict__ input,
    const float* __restrict__ b_l,
    const float* __restrict__ W_fc,
    const float* __restrict__ b_fc,
    float* __restrict__ out)
{
    __shared__ float sA[BM * PAD_A];
    __shared__ float sW[16 * 128];
    __shared__ float sYs[BM];

    const int s   = blockIdx.y;
    const int nb  = blockIdx.x * BM;
    const int tid = threadIdx.x;
    const int tx  = tid & 15;
    const int ty  = tid >> 4;
    const float* xs_base = input + (size_t)s * NNODES * D;
    const float* ag_base = g_agg + (size_t)s * NNODES * D;

    float acc[8][8];
#pragma unroll
    for (int i = 0; i < 8; i++)
#pragma unroll
        for (int jj = 0; jj < 8; jj++) acc[i][jj] = 0.f;

    const int lm  = tid >> 1;
    const int lks = (tid & 1) * 8;

    for (int kc = 0; kc < 16; kc++) {
        float4 a0 = make_float4(0, 0, 0, 0), a1 = make_float4(0, 0, 0, 0);
        int n = nb + lm;
        if (n < NNODES) {
            const float* src = (kc < 8)
                ? ag_base + (size_t)n * D + kc * 16 + lks
                : xs_base + (size_t)n * D + (kc - 8) * 16 + lks;
            a0 = *(const float4*)src;
            a1 = *(const float4*)(src + 4);
        }
        float4 w0 = *(const float4*)&g_WT[kc * 16 * 128 + tid * 8];
        float4 w1 = *(const float4*)&g_WT[kc * 16 * 128 + tid * 8 + 4];

        __syncthreads();
        *(float4*)&sA[lm * PAD_A + lks]     = a0;
        *(float4*)&sA[lm * PAD_A + lks + 4] = a1;
        *(float4*)&sW[tid * 8]     = w0;
        *(float4*)&sW[tid * 8 + 4] = w1;
        __syncthreads();

#pragma unroll
        for (int kl = 0; kl < 16; kl++) {
            float4 wv0 = *(const float4*)&sW[kl * 128 + tx * 8];
            float4 wv1 = *(const float4*)&sW[kl * 128 + tx * 8 + 4];
            float wv[8] = { wv0.x, wv0.y, wv0.z, wv0.w, wv1.x, wv1.y, wv1.z, wv1.w };
#pragma unroll
            for (int i = 0; i < 8; i++) {
                float a = sA[(ty * 8 + i) * PAD_A + kl];
#pragma unroll
                for (int jj = 0; jj < 8; jj++) acc[i][jj] += a * wv[jj];
            }
        }
    }

    float4 bl0 = *(const float4*)&b_l[tx * 8];
    float4 bl1 = *(const float4*)&b_l[tx * 8 + 4];
    float bl[8] = { bl0.x, bl0.y, bl0.z, bl0.w, bl1.x, bl1.y, bl1.z, bl1.w };
    float4 wf0 = *(const float4*)&W_fc[tx * 8];
    float4 wf1 = *(const float4*)&W_fc[tx * 8 + 4];
    float wf[8] = { wf0.x, wf0.y, wf0.z, wf0.w, wf1.x, wf1.y, wf1.z, wf1.w };

#pragma unroll
    for (int i = 0; i < 8; i++) {
        int m = ty * 8 + i;
        int n = nb + m;
        float p = 0.f;
#pragma unroll
        for (int jj = 0; jj < 8; jj++) {
            acc[i][jj] += bl[jj];
            p += acc[i][jj] * wf[jj];
        }
        for (int off = 8; off > 0; off >>= 1)
            p += __shfl_down_sync(0xffffffffu, p, off, 16);
        if (tx == 0) sYs[m] = p;
        if (n < NNODES) {
            float* op = out + ((size_t)s * NNODES + n) * D + tx * 8;
            *(float4*)op       = make_float4(acc[i][0], acc[i][1], acc[i][2], acc[i][3]);
            *(float4*)(op + 4) = make_float4(acc[i][4], acc[i][5], acc[i][6], acc[i][7]);
        }
    }
    __syncthreads();
    if (tid < BM) {
        int n = nb + tid;
        if (n < NNODES)
            out[(size_t)SSTEPS * NNODES * D + (size_t)s * NNODES + n] = sYs[tid] + b_fc[0];
    }
}

// ---------------- launch ----------------
extern "C" void kernel_launch(void* const* d_in, const int* in_sizes, int n_in,
                              void* d_out, int out_size) {
    const float* input = (const float*)d_in[0];
    const int*   ei    = (const int*)d_in[1];      // int32 (JAX x64 disabled)
    const float* W_l   = (const float*)d_in[2];
    const float* b_l   = (const float*)d_in[3];
    const float* W_r   = (const float*)d_in[4];
    const float* W_fc  = (const float*)d_in[5];
    const float* b_fc  = (const float*)d_in[6];
    float* out = (float*)d_out;

    k_init <<<(NNODES + 255) / 256, 256>>>();
    k_count<<<(NE / 4 + 255) / 256, 256>>>(ei);
    k_scan <<<1, 256>>>();
    k_fill <<<(NE / 4 + 255) / 256, 256>>>(ei);
    k_wt   <<<(2 * D * D + 255) / 256, 256>>>(W_l, W_r);

    const size_t total = (size_t)SSTEPS * NNODES * D;
    k_tohalf<<<(unsigned)((total / 4 + 255) / 256), 256>>>(input);

    dim3 agrid((NNODES * 32 + 255) / 256, SSTEPS);
    k_agg<<<agrid, 256>>>();

    dim3 ggrid((NNODES + BM - 1) / BM, SSTEPS);
    k_gemm<<<ggrid, 256>>>(input, b_l, W_fc, b_fc, out);
}

// round 7
// speedup vs baseline: 1.9764x; 1.7317x over previous
#include <cuda_runtime.h>
#include <cuda_fp16.h>
#include <cstdint>

#define SSTEPS 8
#define NNODES 50000
#define D 128
#define NE 1600000

#define BM 128
#define PITCH 24   // smem row pitch in halves (48 B, 16B-aligned)

// ---- device scratch (static; no runtime allocation) ----
__device__ __align__(16) int    g_deg[NNODES];
__device__ __align__(16) int    g_cursor[NNODES];
__device__ __align__(16) int    g_rowptr[NNODES + 1];
__device__ __align__(16) int    g_col[NE];
__device__ __align__(16) float  g_invdeg[NNODES];
__device__ __align__(16) __half g_Wh[D * 2 * D];                        // [j][k] k<128->W_l, else W_r
__device__ __align__(16) __half g_xh[(size_t)SSTEPS * NNODES * D];     // fp16 x
__device__ __align__(16) __half g_aggh[(size_t)SSTEPS * NNODES * D];   // fp16 mean agg

// ---------------- CSR build ----------------
__global__ void k_init() {
    int i = blockIdx.x * blockDim.x + threadIdx.x;
    if (i < NNODES) { g_deg[i] = 0; g_cursor[i] = 0; }
}

__global__ void k_count(const int* __restrict__ ei) {
    int e4 = (blockIdx.x * blockDim.x + threadIdx.x) * 4;
    if (e4 < NE) {
        int4 d = *(const int4*)(ei + NE + e4);
        atomicAdd(&g_deg[d.x], 1);
        atomicAdd(&g_deg[d.y], 1);
        atomicAdd(&g_deg[d.z], 1);
        atomicAdd(&g_deg[d.w], 1);
    }
}

__global__ void k_scan() {
    __shared__ int sbuf[256];
    __shared__ int s_carry;
    if (threadIdx.x == 0) s_carry = 0;
    __syncthreads();
    const int nchunk = (NNODES + 255) / 256;
    for (int c = 0; c < nchunk; c++) {
        int idx = c * 256 + threadIdx.x;
        int v = (idx < NNODES) ? g_deg[idx] : 0;
        sbuf[threadIdx.x] = v;
        __syncthreads();
        for (int off = 1; off < 256; off <<= 1) {
            int t = (threadIdx.x >= off) ? sbuf[threadIdx.x - off] : 0;
            __syncthreads();
            sbuf[threadIdx.x] += t;
            __syncthreads();
        }
        int carry = s_carry;
        if (idx < NNODES) {
            g_rowptr[idx] = carry + sbuf[threadIdx.x] - v;
            g_invdeg[idx] = 1.0f / (float)max(v, 1);
        }
        __syncthreads();
        if (threadIdx.x == 255) s_carry = carry + sbuf[255];
        __syncthreads();
    }
    if (threadIdx.x == 0) g_rowptr[NNODES] = s_carry;
}

__global__ void k_fill(const int* __restrict__ ei) {
    int e4 = (blockIdx.x * blockDim.x + threadIdx.x) * 4;
    if (e4 < NE) {
        int4 s = *(const int4*)(ei + e4);
        int4 d = *(const int4*)(ei + NE + e4);
        int p;
        p = atomicAdd(&g_cursor[d.x], 1); g_col[g_rowptr[d.x] + p] = s.x;
        p = atomicAdd(&g_cursor[d.y], 1); g_col[g_rowptr[d.y] + p] = s.y;
        p = atomicAdd(&g_cursor[d.z], 1); g_col[g_rowptr[d.z] + p] = s.z;
        p = atomicAdd(&g_cursor[d.w], 1); g_col[g_rowptr[d.w] + p] = s.w;
    }
}

// weights -> fp16 [j][k] (k<128: W_l, else W_r); this is the row.col B operand
__global__ void k_wh(const float* __restrict__ Wl, const float* __restrict__ Wr) {
    int i = blockIdx.x * blockDim.x + threadIdx.x;
    if (i < D * 2 * D) {
        int j = i / (2 * D), k = i % (2 * D);
        float v = (k < D) ? Wl[j * D + k] : Wr[j * D + (k - D)];
        g_Wh[i] = __float2half_rn(v);
    }
}

__global__ void __launch_bounds__(256) k_tohalf(const float* __restrict__ input) {
    size_t i = (size_t)(blockIdx.x * blockDim.x + threadIdx.x) * 4;
    const size_t total = (size_t)SSTEPS * NNODES * D;
    if (i < total) {
        float4 v = *(const float4*)(input + i);
        __half2 h0 = __floats2half2_rn(v.x, v.y);
        __half2 h1 = __floats2half2_rn(v.z, v.w);
        uint2 u;
        u.x = *reinterpret_cast<unsigned*>(&h0);
        u.y = *reinterpret_cast<unsigned*>(&h1);
        *(uint2*)(g_xh + i) = u;
    }
}

// ---------------- gather mean aggregation (fp16 in/out, fp32 accum) ----------------
__global__ void __launch_bounds__(256) k_agg() {
    int gw = (blockIdx.x * blockDim.x + threadIdx.x) >> 5;
    if (gw >= NNODES) return;
    const int lane = threadIdx.x & 31;
    const int h = lane >> 4;
    const int q = lane & 15;
    const int n = gw;
    const int s = blockIdx.y;
    const __half* bp = g_xh + (size_t)s * NNODES * D + q * 8;

    float acc[8];
#pragma unroll
    for (int i = 0; i < 8; i++) acc[i] = 0.f;

#define ACC_U4(u) {                                                        \
        __half2 p0 = *reinterpret_cast<__half2*>(&u.x);                    \
        __half2 p1 = *reinterpret_cast<__half2*>(&u.y);                    \
        __half2 p2 = *reinterpret_cast<__half2*>(&u.z);                    \
        __half2 p3 = *reinterpret_cast<__half2*>(&u.w);                    \
        float2 f0 = __half22float2(p0); float2 f1 = __half22float2(p1);    \
        float2 f2 = __half22float2(p2); float2 f3 = __half22float2(p3);    \
        acc[0] += f0.x; acc[1] += f0.y; acc[2] += f1.x; acc[3] += f1.y;    \
        acc[4] += f2.x; acc[5] += f2.y; acc[6] += f3.x; acc[7] += f3.y; }

    const int beg = g_rowptr[n];
    const int end = g_rowptr[n + 1];
    int j = beg;
    for (; j + 8 <= end; j += 8) {
        int c0 = g_col[j + 0 + h];
        int c1 = g_col[j + 2 + h];
        int c2 = g_col[j + 4 + h];
        int c3 = g_col[j + 6 + h];
        uint4 u0 = *(const uint4*)(bp + (size_t)c0 * D);
        uint4 u1 = *(const uint4*)(bp + (size_t)c1 * D);
        uint4 u2 = *(const uint4*)(bp + (size_t)c2 * D);
        uint4 u3 = *(const uint4*)(bp + (size_t)c3 * D);
        ACC_U4(u0) ACC_U4(u1) ACC_U4(u2) ACC_U4(u3)
    }
    for (; j + 2 <= end; j += 2) {
        int c = g_col[j + h];
        uint4 u = *(const uint4*)(bp + (size_t)c * D);
        ACC_U4(u)
    }
    if (j < end && h == 0) {
        int c = g_col[j];
        uint4 u = *(const uint4*)(bp + (size_t)c * D);
        ACC_U4(u)
    }
#undef ACC_U4

#pragma unroll
    for (int i = 0; i < 8; i++)
        acc[i] += __shfl_down_sync(0xffffffffu, acc[i], 16);

    if (h == 0) {
        float inv = g_invdeg[n];
        __half2 h0 = __floats2half2_rn(acc[0] * inv, acc[1] * inv);
        __half2 h1 = __floats2half2_rn(acc[2] * inv, acc[3] * inv);
        __half2 h2 = __floats2half2_rn(acc[4] * inv, acc[5] * inv);
        __half2 h3 = __floats2half2_rn(acc[6] * inv, acc[7] * inv);
        uint4 u;
        u.x = *reinterpret_cast<unsigned*>(&h0);
        u.y = *reinterpret_cast<unsigned*>(&h1);
        u.z = *reinterpret_cast<unsigned*>(&h2);
        u.w = *reinterpret_cast<unsigned*>(&h3);
        *(uint4*)(g_aggh + ((size_t)s * NNODES + n) * D + q * 8) = u;
    }
}

// ---------------- tensor-core GEMM + head ----------------
#define LDSM4(r0, r1, r2, r3, a) \
    asm volatile("ldmatrix.sync.aligned.m8n8.x4.shared.b16 {%0,%1,%2,%3},[%4];" \
                 : "=r"(r0), "=r"(r1), "=r"(r2), "=r"(r3) : "r"(a))
#define MMA16816(c0, c1, c2, c3, a0, a1, a2, a3, b0, b1) \
    asm volatile("mma.sync.aligned.m16n8k16.row.col.f32.f16.f16.f32 " \
                 "{%0,%1,%2,%3},{%4,%5,%6,%7},{%8,%9},{%0,%1,%2,%3};" \
                 : "+f"(c0), "+f"(c1), "+f"(c2), "+f"(c3) \
                 : "r"(a0), "r"(a1), "r"(a2), "r"(a3), "r"(b0), "r"(b1))

// grid (ceil(N/128), S), 256 threads = 8 warps; warp w -> rows [16w,16w+16), all 128 cols
__global__ void __launch_bounds__(256) k_gemm_tc(
    const float* __restrict__ b_l,
    const float* __restrict__ W_fc,
    const float* __restrict__ b_fc,
    float* __restrict__ out)
{
    __shared__ __half sA[BM * PITCH];
    __shared__ __half sB[BM * PITCH];
    __shared__ float  sYs[BM];

    const int s    = blockIdx.y;
    const int nb   = blockIdx.x * BM;
    const int tid  = threadIdx.x;
    const int warp = tid >> 5;
    const int lane = tid & 31;

    const __half* ab = g_aggh + (size_t)s * NNODES * D;
    const __half* xb = g_xh   + (size_t)s * NNODES * D;

    float c[16][4];
#pragma unroll
    for (int nt = 0; nt < 16; nt++)
#pragma unroll
        for (int r = 0; r < 4; r++) c[nt][r] = 0.f;

    // staging: thread -> (row = tid/2, 8 halves at koff)
    const int srow = tid >> 1;
    const int koff = (tid & 1) * 8;

    // ldmatrix addresses
    const uint32_t sA_u = (uint32_t)__cvta_generic_to_shared(sA);
    const uint32_t sB_u = (uint32_t)__cvta_generic_to_shared(sB);
    const uint32_t a_addr = sA_u + (uint32_t)(((warp * 16 + (lane & 15)) * PITCH + (lane >> 4) * 8) * 2);
    const int l8  = lane & 7;
    const int seg = lane >> 3;   // 0..3
    const uint32_t b_base = sB_u + (uint32_t)((((seg >> 1) * 8 + l8) * PITCH + (seg & 1) * 8) * 2);

    for (int kc = 0; kc < 16; kc++) {
        uint4 av = make_uint4(0, 0, 0, 0);
        int n = nb + srow;
        if (n < NNODES) {
            const __half* src = (kc < 8)
                ? ab + (size_t)n * D + kc * 16 + koff
                : xb + (size_t)n * D + (kc - 8) * 16 + koff;
            av = *(const uint4*)src;
        }
        uint4 bv = *(const uint4*)(g_Wh + srow * (2 * D) + kc * 16 + koff);
        __syncthreads();
        *(uint4*)&sA[srow * PITCH + koff] = av;
        *(uint4*)&sB[srow * PITCH + koff] = bv;
        __syncthreads();

        uint32_t a0, a1, a2, a3;
        LDSM4(a0, a1, a2, a3, a_addr);

#pragma unroll
        for (int p = 0; p < 8; p++) {
            uint32_t b00, b01, b10, b11;   // ntile 2p (k0,k8), ntile 2p+1 (k0,k8)
            LDSM4(b00, b01, b10, b11, b_base + (uint32_t)(p * 16 * PITCH * 2));
            MMA16816(c[2*p][0],   c[2*p][1],   c[2*p][2],   c[2*p][3],   a0, a1, a2, a3, b00, b01);
            MMA16816(c[2*p+1][0], c[2*p+1][1], c[2*p+1][2], c[2*p+1][3], a0, a1, a2, a3, b10, b11);
        }
    }

    // ---- epilogue: + b_l, write xs, ys dot ----
    const int qt = lane & 3;
    const int r4 = lane >> 2;
    const int m0 = warp * 16 + r4;
    const int m1 = m0 + 8;
    const int n0 = nb + m0;
    const int n1 = nb + m1;
    float ys0 = 0.f, ys1 = 0.f;

#pragma unroll
    for (int nt = 0; nt < 16; nt++) {
        int j = nt * 8 + qt * 2;
        float2 bl = *(const float2*)&b_l[j];
        float2 wf = *(const float2*)&W_fc[j];
        c[nt][0] += bl.x; c[nt][1] += bl.y;
        c[nt][2] += bl.x; c[nt][3] += bl.y;
        ys0 += c[nt][0] * wf.x + c[nt][1] * wf.y;
        ys1 += c[nt][2] * wf.x + c[nt][3] * wf.y;
        if (n0 < NNODES)
            *(float2*)&out[((size_t)s * NNODES + n0) * D + j] = make_float2(c[nt][0], c[nt][1]);
        if (n1 < NNODES)
            *(float2*)&out[((size_t)s * NNODES + n1) * D + j] = make_float2(c[nt][2], c[nt][3]);
    }
    ys0 += __shfl_xor_sync(0xffffffffu, ys0, 1);
    ys0 += __shfl_xor_sync(0xffffffffu, ys0, 2);
    ys1 += __shfl_xor_sync(0xffffffffu, ys1, 1);
    ys1 += __shfl_xor_sync(0xffffffffu, ys1, 2);
    if (qt == 0) { sYs[m0] = ys0; sYs[m1] = ys1; }
    __syncthreads();
    if (tid < BM) {
        int n = nb + tid;
        if (n < NNODES)
            out[(size_t)SSTEPS * NNODES * D + (size_t)s * NNODES + n] = sYs[tid] + b_fc[0];
    }
}

// ---------------- launch ----------------
extern "C" void kernel_launch(void* const* d_in, const int* in_sizes, int n_in,
                              void* d_out, int out_size) {
    const float* input = (const float*)d_in[0];
    const int*   ei    = (const int*)d_in[1];      // int32 (JAX x64 disabled)
    const float* W_l   = (const float*)d_in[2];
    const float* b_l   = (const float*)d_in[3];
    const float* W_r   = (const float*)d_in[4];
    const float* W_fc  = (const float*)d_in[5];
    const float* b_fc  = (const float*)d_in[6];
    float* out = (float*)d_out;

    k_init <<<(NNODES + 255) / 256, 256>>>();
    k_count<<<(NE / 4 + 255) / 256, 256>>>(ei);
    k_scan <<<1, 256>>>();
    k_fill <<<(NE / 4 + 255) / 256, 256>>>(ei);
    k_wh   <<<(D * 2 * D + 255) / 256, 256>>>(W_l, W_r);

    const size_t total = (size_t)SSTEPS * NNODES * D;
    k_tohalf<<<(unsigned)((total / 4 + 255) / 256), 256>>>(input);

    dim3 agrid((NNODES * 32 + 255) / 256, SSTEPS);
    k_agg<<<agrid, 256>>>();

    dim3 ggrid((NNODES + BM - 1) / BM, SSTEPS);
    k_gemm_tc<<<ggrid, 256>>>(b_l, W_fc, b_fc, out);
}